// round 1
// baseline (speedup 1.0000x reference)
#include <cuda_runtime.h>

#define BB 32
#define SS 16
#define FF 2048
#define NCH 8
#define FCH 256

// Scratch (device globals — no allocations allowed)
__device__ float g_part[BB * NCH * FF];        // partial exp-sums over f-chunks: (b, fchunk, g)
__device__ float g_Cpart[BB * NCH * SS * SS];  // Gram partials over g-chunks
__device__ float g_E[BB * SS * SS];            // folded gate weights  [b][s][so]
__device__ float g_const[BB * SS];             // folded gate constants [b][so]

// ---------------------------------------------------------------------------
// Kernel A: Gram partials  Cpart[b,gc,s1,s2] = sum_{g in chunk} attn[b,s1,g]*attn[b,s2,g]
// ---------------------------------------------------------------------------
__global__ void __launch_bounds__(256) gram_kernel(const float* __restrict__ attn) {
    int b = blockIdx.x, gc = blockIdx.y;
    __shared__ float sm[SS * 257];  // pad to 257 to avoid bank conflicts
    int tid = threadIdx.x;
    int gbase = gc * FCH;
    for (int idx = tid; idx < SS * FCH; idx += 256) {
        int s = idx >> 8, j = idx & 255;
        sm[s * 257 + j] = attn[(b * SS + s) * FF + gbase + j];
    }
    __syncthreads();
    int s1 = tid >> 4, s2 = tid & 15;
    float acc = 0.f;
#pragma unroll 8
    for (int j = 0; j < FCH; j++)
        acc = fmaf(sm[s1 * 257 + j], sm[s2 * 257 + j], acc);
    g_Cpart[((b * NCH + gc) * SS + s1) * SS + s2] = acc;
}

// ---------------------------------------------------------------------------
// Kernel B: partial exp-sums.
// Block (b, fchunk). 512 threads, each owns 4 g-columns (attn kept in regs),
// inp broadcast from smem. acc[g] += exp( sum_s inp[s,f]*attn[s,g] ).
// ---------------------------------------------------------------------------
__global__ void __launch_bounds__(512) expsum_kernel(const float* __restrict__ data,
                                                     const float* __restrict__ attn) {
    int b = blockIdx.x, fc = blockIdx.y;
    int tid = threadIdx.x;
    __shared__ float smi[SS * FCH];  // 16 KB inp chunk
    int fbase = fc * FCH;
    for (int idx = tid; idx < SS * FCH; idx += 512) {
        int s = idx >> 8, j = idx & 255;
        smi[idx] = data[(b * SS + s) * FF + fbase + j];
    }
    float av0[SS], av1[SS], av2[SS], av3[SS];
#pragma unroll
    for (int s = 0; s < SS; s++) {
        const float* ar = &attn[(b * SS + s) * FF];
        av0[s] = ar[tid];
        av1[s] = ar[tid + 512];
        av2[s] = ar[tid + 1024];
        av3[s] = ar[tid + 1536];
    }
    __syncthreads();
    float acc0 = 0.f, acc1 = 0.f, acc2 = 0.f, acc3 = 0.f;
    for (int f = 0; f < FCH; f++) {
        float iv[SS];
#pragma unroll
        for (int s = 0; s < SS; s++) iv[s] = smi[s * FCH + f];  // broadcast LDS
        float m0 = 0.f, m1 = 0.f, m2 = 0.f, m3 = 0.f;
#pragma unroll
        for (int s = 0; s < SS; s++) {
            m0 = fmaf(iv[s], av0[s], m0);
            m1 = fmaf(iv[s], av1[s], m1);
            m2 = fmaf(iv[s], av2[s], m2);
            m3 = fmaf(iv[s], av3[s], m3);
        }
        acc0 += __expf(m0);
        acc1 += __expf(m1);
        acc2 += __expf(m2);
        acc3 += __expf(m3);
    }
    float* gp = &g_part[(b * NCH + fc) * FF];
    gp[tid] = acc0;
    gp[tid + 512] = acc1;
    gp[tid + 1024] = acc2;
    gp[tid + 1536] = acc3;
}

// ---------------------------------------------------------------------------
// Kernel C: per-batch finish.  LSE -> D -> E/const.
// ---------------------------------------------------------------------------
__global__ void __launch_bounds__(512) finish_kernel(const float* __restrict__ attn,
                                                     const float* __restrict__ W,
                                                     const float* __restrict__ bias) {
    int b = blockIdx.x;
    int tid = threadIdx.x;
    __shared__ float lse[FF];  // 8 KB
    __shared__ float Csm[SS * SS];
    __shared__ float Dsm[SS];

    // LSE[b,g] = log( sum of f-chunk partials )
    for (int g = tid; g < FF; g += 512) {
        float s = 0.f;
#pragma unroll
        for (int c = 0; c < NCH; c++) s += g_part[(b * NCH + c) * FF + g];
        lse[g] = logf(s);
    }
    if (tid < 256) {
        float s = 0.f;
#pragma unroll
        for (int c = 0; c < NCH; c++) s += g_Cpart[(b * NCH + c) * SS * SS + tid];
        Csm[tid] = s;
    }
    __syncthreads();

    // D[b,s2] = sum_g lse[g]*attn[b,s2,g]  (warp per s2)
    {
        int w = tid >> 5, lane = tid & 31;
        float p = 0.f;
        const float* arow = &attn[(b * SS + w) * FF];
        for (int g = lane; g < FF; g += 32) p = fmaf(lse[g], arow[g], p);
#pragma unroll
        for (int o = 16; o; o >>= 1) p += __shfl_xor_sync(0xffffffffu, p, o);
        if (lane == 0) Dsm[w] = p;
    }
    __syncthreads();

    // E[b,s,so] = sum_k C[s,k]*W[so,k] + W[so,16+s]
    if (tid < 256) {
        int s = tid >> 4, so = tid & 15;
        float e = W[so * 32 + 16 + s];
#pragma unroll
        for (int k = 0; k < SS; k++) e = fmaf(Csm[s * SS + k], W[so * 32 + k], e);
        g_E[b * 256 + tid] = e;
    }
    // const[b,so] = bias[so] - sum_k D[k]*W[so,k]
    if (tid < 16) {
        float c = bias[tid];
#pragma unroll
        for (int k = 0; k < SS; k++) c = fmaf(-Dsm[k], W[tid * 32 + k], c);
        g_const[b * SS + tid] = c;
    }
}

// ---------------------------------------------------------------------------
// Kernel D: final output.
// out[so*32+bb, f] = sigmoid( sum_s data[bb*16+s,f]*E[bb,s,so] + const[bb,so] )
//                    * data[so*32+bb, f]
// ---------------------------------------------------------------------------
__global__ void __launch_bounds__(128) final_kernel(const float* __restrict__ data,
                                                    float* __restrict__ out) {
    int bb = blockIdx.x;  // 0..31
    int ft = blockIdx.y;  // 0..15
    int tid = threadIdx.x;
    __shared__ float Esm[256];
    __shared__ float Km[16];
    for (int i = tid; i < 256; i += 128) Esm[i] = g_E[bb * 256 + i];
    if (tid < 16) Km[tid] = g_const[bb * SS + tid];
    __syncthreads();

    int f = ft * 128 + tid;
    float din[SS];
#pragma unroll
    for (int s = 0; s < SS; s++) din[s] = data[(bb * SS + s) * FF + f];
#pragma unroll
    for (int so = 0; so < SS; so++) {
        float z = Km[so];
#pragma unroll
        for (int s = 0; s < SS; s++) z = fmaf(din[s], Esm[s * 16 + so], z);
        float gate = 1.f / (1.f + __expf(-z));
        int row = so * 32 + bb;
        out[row * FF + f] = gate * data[row * FF + f];
    }
}

// ---------------------------------------------------------------------------
extern "C" void kernel_launch(void* const* d_in, const int* in_sizes, int n_in,
                              void* d_out, int out_size) {
    const float* data = (const float*)d_in[0];
    const float* attn = (const float*)d_in[1];
    const float* W = (const float*)d_in[2];
    const float* bias = (const float*)d_in[3];
    float* out = (float*)d_out;

    gram_kernel<<<dim3(BB, NCH), 256>>>(attn);
    expsum_kernel<<<dim3(BB, NCH), 512>>>(data, attn);
    finish_kernel<<<BB, 512>>>(attn, W, bias);
    final_kernel<<<dim3(BB, 16), 128>>>(data, out);
}

// round 4
// speedup vs baseline: 1.1728x; 1.1728x over previous
#include <cuda_runtime.h>

#define BB 32
#define SS 16
#define FF 2048
#define NCH 8
#define FCH 256
#define EXPB 148
#define TOTAL (BB * FF)

typedef unsigned long long ull;

// Scratch (device globals — no allocations allowed)
__device__ float g_part[BB * NCH * FF];        // exp-sum partials: (b, slot, g)
__device__ float g_Cpart[BB * NCH * SS * SS];  // Gram partials over g-chunks
__device__ float g_Dpart[BB * NCH * SS];       // D partials over g-chunks
__device__ float g_E[BB * SS * SS];            // folded gate weights  [b][s][so]
__device__ float g_const[BB * SS];             // folded gate constants [b][so]

// ---------------------------------------------------------------------------
// Kernel A: Gram partials + zero g_part.
// ---------------------------------------------------------------------------
__global__ void __launch_bounds__(256) gram_kernel(const float* __restrict__ attn) {
    int b = blockIdx.x, gc = blockIdx.y;
    __shared__ float sm[SS * 257];
    int tid = threadIdx.x;
    int gbase = gc * FCH;
    // zero the exp-sum partial slab for this (b, slot)
    float* zp = &g_part[(b * NCH + gc) * FF];
#pragma unroll
    for (int k = 0; k < 8; k++) zp[k * 256 + tid] = 0.f;
    for (int idx = tid; idx < SS * FCH; idx += 256) {
        int s = idx >> 8, j = idx & 255;
        sm[s * 257 + j] = attn[(b * SS + s) * FF + gbase + j];
    }
    __syncthreads();
    int s1 = tid >> 4, s2 = tid & 15;
    float acc = 0.f;
#pragma unroll 8
    for (int j = 0; j < FCH; j++)
        acc = fmaf(sm[s1 * 257 + j], sm[s2 * 257 + j], acc);
    g_Cpart[((b * NCH + gc) * SS + s1) * SS + s2] = acc;
}

// ---------------------------------------------------------------------------
// Kernel B: exp-sums, persistent (grid=148), packed f32x2 FMA.
// Each thread owns 4 g-columns as two f32x2 pairs (attn*log2e in regs).
// data broadcast from smem as duplicated float2 (LDS.64 -> FFMA2 operand).
// ---------------------------------------------------------------------------
__global__ void __launch_bounds__(512) expsum_kernel(const float* __restrict__ data,
                                                     const float* __restrict__ attn) {
    int tid = threadIdx.x;
    __shared__ float2 smi[SS * FCH];  // 32 KB, each entry = (v, v)

    int i0 = (int)(((long long)blockIdx.x * TOTAL) / EXPB);
    int i1 = (int)(((long long)(blockIdx.x + 1) * TOTAL) / EXPB);
    int i = i0;
    const float LOG2E = 1.442695040888963f;

    while (i < i1) {
        int b = i >> 11;
        int fb = i & 2047;
        int fend = fb + (i1 - i);
        if (fend > 2048) fend = 2048;

        // attn columns into regs, pre-scaled by log2e
        ull av0[SS], av1[SS];
#pragma unroll
        for (int s = 0; s < SS; s++) {
            const float2* ar = (const float2*)&attn[(b * SS + s) * FF];
            float2 v0 = ar[tid];        // g = 2*tid, 2*tid+1
            float2 v1 = ar[tid + 512];  // g = 1024 + 2*tid, +1
            float a0 = v0.x * LOG2E, a1 = v0.y * LOG2E;
            float a2 = v1.x * LOG2E, a3 = v1.y * LOG2E;
            asm("mov.b64 %0, {%1,%2};" : "=l"(av0[s]) : "f"(a0), "f"(a1));
            asm("mov.b64 %0, {%1,%2};" : "=l"(av1[s]) : "f"(a2), "f"(a3));
        }
        ull acc0 = 0ull, acc1 = 0ull;  // two packed 0.0f

        for (int f0 = fb; f0 < fend; f0 += FCH) {
            int fn = fend - f0;
            if (fn > FCH) fn = FCH;
            __syncthreads();
            for (int idx = tid; idx < SS * FCH; idx += 512) {
                int s = idx >> 8, f = idx & 255;
                if (f < fn) {
                    float v = data[(b * SS + s) * FF + f0 + f];
                    smi[idx] = make_float2(v, v);
                }
            }
            __syncthreads();
            const ull* smu = (const ull*)smi;
            for (int f = 0; f < fn; f++) {
                ull m0 = 0ull, m1 = 0ull;
#pragma unroll
                for (int s = 0; s < SS; s++) {
                    ull iv = smu[s * FCH + f];
                    asm("fma.rn.f32x2 %0, %1, %2, %0;" : "+l"(m0) : "l"(iv), "l"(av0[s]));
                    asm("fma.rn.f32x2 %0, %1, %2, %0;" : "+l"(m1) : "l"(iv), "l"(av1[s]));
                }
                float x0, x1, x2, x3;
                asm("mov.b64 {%0,%1}, %2;" : "=f"(x0), "=f"(x1) : "l"(m0));
                asm("mov.b64 {%0,%1}, %2;" : "=f"(x2), "=f"(x3) : "l"(m1));
                float e0, e1, e2, e3;
                asm("ex2.approx.f32 %0, %1;" : "=f"(e0) : "f"(x0));
                asm("ex2.approx.f32 %0, %1;" : "=f"(e1) : "f"(x1));
                asm("ex2.approx.f32 %0, %1;" : "=f"(e2) : "f"(x2));
                asm("ex2.approx.f32 %0, %1;" : "=f"(e3) : "f"(x3));
                ull p0, p1;
                asm("mov.b64 %0, {%1,%2};" : "=l"(p0) : "f"(e0), "f"(e1));
                asm("mov.b64 %0, {%1,%2};" : "=l"(p1) : "f"(e2), "f"(e3));
                asm("add.rn.f32x2 %0, %0, %1;" : "+l"(acc0) : "l"(p0));
                asm("add.rn.f32x2 %0, %0, %1;" : "+l"(acc1) : "l"(p1));
            }
        }

        // flush partials for this b to a unique (b, slot)
        int ref = (int)(((long long)b * 2048 * EXPB) / TOTAL);
        int slot = (int)blockIdx.x - ref;
        float s0, s1, s2, s3;
        asm("mov.b64 {%0,%1}, %2;" : "=f"(s0), "=f"(s1) : "l"(acc0));
        asm("mov.b64 {%0,%1}, %2;" : "=f"(s2), "=f"(s3) : "l"(acc1));
        float* gp = &g_part[(b * NCH + slot) * FF];
        gp[2 * tid] = s0;
        gp[2 * tid + 1] = s1;
        gp[1024 + 2 * tid] = s2;
        gp[1024 + 2 * tid + 1] = s3;

        i += (fend - fb);
    }
}

// ---------------------------------------------------------------------------
// Kernel C1: per-(b, g-chunk) LSE + partial D.
// D[b,s] = sum_g log(sum_f exp(M))*attn[b,s,g]
// ---------------------------------------------------------------------------
__global__ void __launch_bounds__(256) dpart_kernel(const float* __restrict__ attn) {
    int b = blockIdx.x, gc = blockIdx.y;
    int tid = threadIdx.x;
    __shared__ float lse[FCH];
    int g = gc * FCH + tid;
    {
        float s = 0.f;
#pragma unroll
        for (int c = 0; c < NCH; c++) s += g_part[(b * NCH + c) * FF + g];
        lse[tid] = logf(s);
    }
    __syncthreads();
    int w = tid >> 5, lane = tid & 31;
#pragma unroll
    for (int h = 0; h < 2; h++) {
        int s2 = 2 * w + h;
        const float* arow = &attn[(b * SS + s2) * FF + gc * FCH];
        float p = 0.f;
#pragma unroll
        for (int k = 0; k < FCH / 32; k++) p = fmaf(lse[lane + k * 32], arow[lane + k * 32], p);
#pragma unroll
        for (int o = 16; o; o >>= 1) p += __shfl_xor_sync(0xffffffffu, p, o);
        if (lane == 0) g_Dpart[(b * NCH + gc) * SS + s2] = p;
    }
}

// ---------------------------------------------------------------------------
// Kernel C2: combine -> E, const (tiny).
// ---------------------------------------------------------------------------
__global__ void __launch_bounds__(256) combine_kernel(const float* __restrict__ W,
                                                      const float* __restrict__ bias) {
    int b = blockIdx.x;
    int tid = threadIdx.x;
    __shared__ float Csm[SS * SS];
    __shared__ float Dsm[SS];
    {
        float s = 0.f;
#pragma unroll
        for (int c = 0; c < NCH; c++) s += g_Cpart[(b * NCH + c) * SS * SS + tid];
        Csm[tid] = s;
    }
    if (tid < 16) {
        float d = 0.f;
#pragma unroll
        for (int c = 0; c < NCH; c++) d += g_Dpart[(b * NCH + c) * SS + tid];
        Dsm[tid] = d;
    }
    __syncthreads();
    {
        int s = tid >> 4, so = tid & 15;
        float e = W[so * 32 + 16 + s];
#pragma unroll
        for (int k = 0; k < SS; k++) e = fmaf(Csm[s * SS + k], W[so * 32 + k], e);
        g_E[b * 256 + tid] = e;
    }
    if (tid < 16) {
        float c = bias[tid];
#pragma unroll
        for (int k = 0; k < SS; k++) c = fmaf(-Dsm[k], W[tid * 32 + k], c);
        g_const[b * SS + tid] = c;
    }
}

// ---------------------------------------------------------------------------
// Kernel D: final output, float4 vectorized.
// ---------------------------------------------------------------------------
__global__ void __launch_bounds__(128) final_kernel(const float* __restrict__ data,
                                                    float* __restrict__ out) {
    int bb = blockIdx.x;  // 0..31
    int q = blockIdx.y;   // 0..3
    int tid = threadIdx.x;
    __shared__ float Esm[256];
    __shared__ float Km[16];
    Esm[tid] = g_E[bb * 256 + tid];
    Esm[tid + 128] = g_E[bb * 256 + 128 + tid];
    if (tid < 16) Km[tid] = g_const[bb * SS + tid];
    __syncthreads();

    int c = q * 128 + tid;  // float4 column, 0..511
    const float4* d4 = (const float4*)data;
    float4* o4 = (float4*)out;
    float4 din[SS];
#pragma unroll
    for (int s = 0; s < SS; s++) din[s] = d4[(bb * SS + s) * (FF / 4) + c];
#pragma unroll
    for (int so = 0; so < SS; so++) {
        float k0 = Km[so];
        float zx = k0, zy = k0, zz = k0, zw = k0;
#pragma unroll
        for (int s = 0; s < SS; s++) {
            float e = Esm[s * 16 + so];
            zx = fmaf(din[s].x, e, zx);
            zy = fmaf(din[s].y, e, zy);
            zz = fmaf(din[s].z, e, zz);
            zw = fmaf(din[s].w, e, zw);
        }
        float gx = 1.f / (1.f + __expf(-zx));
        float gy = 1.f / (1.f + __expf(-zy));
        float gz = 1.f / (1.f + __expf(-zz));
        float gw = 1.f / (1.f + __expf(-zw));
        int row = so * 32 + bb;
        float4 dv = d4[row * (FF / 4) + c];
        float4 ov;
        ov.x = gx * dv.x;
        ov.y = gy * dv.y;
        ov.z = gz * dv.z;
        ov.w = gw * dv.w;
        o4[row * (FF / 4) + c] = ov;
    }
}

// ---------------------------------------------------------------------------
extern "C" void kernel_launch(void* const* d_in, const int* in_sizes, int n_in,
                              void* d_out, int out_size) {
    const float* data = (const float*)d_in[0];
    const float* attn = (const float*)d_in[1];
    const float* W = (const float*)d_in[2];
    const float* bias = (const float*)d_in[3];
    float* out = (float*)d_out;

    gram_kernel<<<dim3(BB, NCH), 256>>>(attn);
    expsum_kernel<<<EXPB, 512>>>(data, attn);
    dpart_kernel<<<dim3(BB, NCH), 256>>>(attn);
    combine_kernel<<<BB, 256>>>(W, bias);
    final_kernel<<<dim3(BB, 4), 128>>>(data, out);
}

// round 6
// speedup vs baseline: 1.9681x; 1.6781x over previous
#include <cuda_runtime.h>
#include <cuda_bf16.h>
#include <cstdint>

#define BB 32
#define SS 16
#define FF 2048
#define GT 16       // g-tiles per batch (128 g each)
#define GTILE 128
#define FTILE 128
#define NFT 16
#define BSTRIDE 20  // words per f-row in B smem (conflict-free for fragment loads)

// Scratch (device globals — no allocations allowed)
__device__ float g_Cpart[BB * GT * SS * SS];  // Gram partials per g-tile
__device__ float g_Dpart[BB * GT * SS];       // D partials per g-tile

// pack two fp32 -> bf16x2 {lo=v0, hi=v1}
__device__ __forceinline__ uint32_t pack_bf2(float v0, float v1) {
    uint32_t r;
    asm("cvt.rn.bf16x2.f32 %0, %1, %2;" : "=r"(r) : "f"(v1), "f"(v0));
    return r;
}
// hi/lo split pair: hi = bf16x2(v0,v1), lo = bf16x2(residuals)
__device__ __forceinline__ void mk_pair(float v0, float v1, uint32_t& hi, uint32_t& lo) {
    float h0 = __bfloat162float(__float2bfloat16(v0));
    float h1 = __bfloat162float(__float2bfloat16(v1));
    hi = pack_bf2(v0, v1);
    lo = pack_bf2(v0 - h0, v1 - h1);
}
__device__ __forceinline__ void mma_bf16(float* d, const uint32_t* a, uint32_t b0, uint32_t b1) {
    asm volatile(
        "mma.sync.aligned.m16n8k16.row.col.f32.bf16.bf16.f32 "
        "{%0,%1,%2,%3}, {%4,%5,%6,%7}, {%8,%9}, {%0,%1,%2,%3};"
        : "+f"(d[0]), "+f"(d[1]), "+f"(d[2]), "+f"(d[3])
        : "r"(a[0]), "r"(a[1]), "r"(a[2]), "r"(a[3]), "r"(b0), "r"(b1));
}

// ---------------------------------------------------------------------------
// Kernel 1: tensor-core exp-sum + fused gram + LSE + D-partials.
// Block = (b, gtile of 128 g), 256 threads = 8 warps, warp owns 16 g-rows.
// A = attn[16g x 16s]*log2e as hi/lo fragments (fixed per warp).
// B = data[16s x 8f] hi/lo from double-buffered smem.
// D[g,f] via 3 compensated bf16 MMAs; epilogue ex2 + lane-local accumulate.
// ---------------------------------------------------------------------------
__global__ void __launch_bounds__(256) expsum_mma(const float* __restrict__ data,
                                                  const float* __restrict__ attn) {
    __shared__ float attnS[SS][129];                 // padded: gram reads conflict-free
    __shared__ uint32_t dataB[2][FTILE * BSTRIDE];   // [f][hl*8+kw] bf16x2 words
    __shared__ float red[GTILE];

    int tid = threadIdx.x, wid = tid >> 5, lane = tid & 31;
    int b = blockIdx.x, gt = blockIdx.y;
    int gbase = gt * GTILE;

    // attn tile -> smem (fp32, reused for A frags, gram, D-partials)
#pragma unroll
    for (int i = 0; i < 8; i++) {
        int idx = tid + i * 256;
        int s = idx >> 7, gi = idx & 127;
        attnS[s][gi] = attn[(b * SS + s) * FF + gbase + gi];
    }
    __syncthreads();

    // A fragments (fixed per warp). Rows m = lane/4, lane/4+8 ; cols k = (lane%4)*2 (+8).
    const float LOG2E = 1.442695040888963f;
    int m0 = lane >> 2, k0 = (lane & 3) * 2;
    int gi0 = wid * 16 + m0;
    uint32_t a_hi[4], a_lo[4];
    mk_pair(attnS[k0][gi0] * LOG2E,     attnS[k0 + 1][gi0] * LOG2E,     a_hi[0], a_lo[0]);
    mk_pair(attnS[k0][gi0 + 8] * LOG2E, attnS[k0 + 1][gi0 + 8] * LOG2E, a_hi[1], a_lo[1]);
    mk_pair(attnS[k0 + 8][gi0] * LOG2E, attnS[k0 + 9][gi0] * LOG2E,     a_hi[2], a_lo[2]);
    mk_pair(attnS[k0 + 8][gi0 + 8] * LOG2E, attnS[k0 + 9][gi0 + 8] * LOG2E, a_hi[3], a_lo[3]);

    // B tile converter: warp covers s = {2*wid, 2*wid+1}; lane<16 -> s even.
    // Word kw = s>>1 = wid. lane<16 stores hi words, lane>=16 stores lo words.
    int cs = tid >> 4;        // s index 0..15
    int cf = tid & 15;        // f sub-index
    const float* crow = &data[(b * SS + cs) * FF];
    auto convert = [&](int t, int buf) {
        uint32_t* W = dataB[buf];
#pragma unroll
        for (int j = 0; j < 8; j++) {
            int f = cf + 16 * j;
            float v = crow[t * FTILE + f];
            float l = v - __bfloat162float(__float2bfloat16(v));
            float v_p = __shfl_xor_sync(0xffffffffu, v, 16);
            float l_p = __shfl_xor_sync(0xffffffffu, l, 16);
            if (lane < 16) {
                W[f * BSTRIDE + wid] = pack_bf2(v, v_p);          // lo=s even, hi=s odd
            } else {
                W[f * BSTRIDE + 8 + wid] = pack_bf2(l_p, l);
            }
        }
    };

    float acc0 = 0.f, acc1 = 0.f;
    int nidx = lane >> 2, kq = lane & 3;

    convert(0, 0);
    __syncthreads();
    for (int t = 0; t < NFT; t++) {
        if (t + 1 < NFT) convert(t + 1, (t + 1) & 1);
        const uint32_t* W = dataB[t & 1];
#pragma unroll 4
        for (int nb = 0; nb < 16; nb++) {
            const uint32_t* wp = &W[(nb * 8 + nidx) * BSTRIDE];
            uint32_t bh0 = wp[kq], bh1 = wp[kq + 4];
            uint32_t bl0 = wp[kq + 8], bl1 = wp[kq + 12];
            float d[4] = {0.f, 0.f, 0.f, 0.f};
            mma_bf16(d, a_lo, bh0, bh1);
            mma_bf16(d, a_hi, bl0, bl1);
            mma_bf16(d, a_hi, bh0, bh1);
            float e0, e1, e2, e3;
            asm("ex2.approx.f32 %0, %1;" : "=f"(e0) : "f"(d[0]));
            asm("ex2.approx.f32 %0, %1;" : "=f"(e1) : "f"(d[1]));
            asm("ex2.approx.f32 %0, %1;" : "=f"(e2) : "f"(d[2]));
            asm("ex2.approx.f32 %0, %1;" : "=f"(e3) : "f"(d[3]));
            acc0 += e0 + e1;
            acc1 += e2 + e3;
        }
        __syncthreads();
    }

    // quad-reduce (lanes sharing a D row) -> row exp-sums -> lse
    acc0 += __shfl_xor_sync(0xffffffffu, acc0, 1);
    acc0 += __shfl_xor_sync(0xffffffffu, acc0, 2);
    acc1 += __shfl_xor_sync(0xffffffffu, acc1, 1);
    acc1 += __shfl_xor_sync(0xffffffffu, acc1, 2);
    if (kq == 0) {
        red[gi0] = acc0;
        red[gi0 + 8] = acc1;
    }
    __syncthreads();
    if (tid < 128) red[tid] = logf(red[tid]);
    __syncthreads();

    // D partials: warp w handles s = 2w, 2w+1 over this g-tile
#pragma unroll
    for (int h = 0; h < 2; h++) {
        int s2 = wid * 2 + h;
        float p = 0.f;
#pragma unroll
        for (int k = 0; k < 4; k++) p = fmaf(red[lane + 32 * k], attnS[s2][lane + 32 * k], p);
#pragma unroll
        for (int o = 16; o; o >>= 1) p += __shfl_xor_sync(0xffffffffu, p, o);
        if (lane == 0) g_Dpart[(b * GT + gt) * SS + s2] = p;
    }

    // Gram partial for this g-tile: thread = (s1,s2)
    {
        int s1 = tid >> 4, s2 = tid & 15;
        float acc = 0.f;
#pragma unroll 4
        for (int g = 0; g < GTILE; g++) acc = fmaf(attnS[s1][g], attnS[s2][g], acc);
        g_Cpart[(b * GT + gt) * 256 + tid] = acc;
    }
}

// ---------------------------------------------------------------------------
// Kernel 2: fused combine + final output (float4).
// ---------------------------------------------------------------------------
__global__ void __launch_bounds__(256) final_kernel(const float* __restrict__ data,
                                                    const float* __restrict__ Wm,
                                                    const float* __restrict__ bias,
                                                    float* __restrict__ out) {
    int bb = blockIdx.x, q = blockIdx.y;
    int tid = threadIdx.x;
    __shared__ float Csm[256], Esm[256], Km[16], Dsm[16];

    {
        float cs = 0.f;
#pragma unroll
        for (int c = 0; c < GT; c++) cs += g_Cpart[(bb * GT + c) * 256 + tid];
        Csm[tid] = cs;
    }
    if (tid < 16) {
        float d = 0.f;
#pragma unroll
        for (int gt = 0; gt < GT; gt++) d += g_Dpart[(bb * GT + gt) * SS + tid];
        Dsm[tid] = d;
    }
    __syncthreads();
    {
        int s = tid >> 4, so = tid & 15;
        float e = Wm[so * 32 + 16 + s];
#pragma unroll
        for (int k = 0; k < SS; k++) e = fmaf(Csm[s * SS + k], Wm[so * 32 + k], e);
        Esm[s * 16 + so] = e;
    }
    if (tid < 16) {
        float c = bias[tid];
#pragma unroll
        for (int k = 0; k < SS; k++) c = fmaf(-Dsm[k], Wm[tid * 32 + k], c);
        Km[tid] = c;
    }
    __syncthreads();

    int c = q * 128 + (tid & 127);  // float4 column 0..511
    int half = tid >> 7;            // so range [half*8, half*8+8)
    const float4* d4 = (const float4*)data;
    float4* o4 = (float4*)out;
    float4 din[SS];
#pragma unroll
    for (int s = 0; s < SS; s++) din[s] = d4[(bb * SS + s) * (FF / 4) + c];
#pragma unroll
    for (int i = 0; i < 8; i++) {
        int so = half * 8 + i;
        float k0 = Km[so];
        float zx = k0, zy = k0, zz = k0, zw = k0;
#pragma unroll
        for (int s = 0; s < SS; s++) {
            float e = Esm[s * 16 + so];
            zx = fmaf(din[s].x, e, zx);
            zy = fmaf(din[s].y, e, zy);
            zz = fmaf(din[s].z, e, zz);
            zw = fmaf(din[s].w, e, zw);
        }
        float gx = 1.f / (1.f + __expf(-zx));
        float gy = 1.f / (1.f + __expf(-zy));
        float gz = 1.f / (1.f + __expf(-zz));
        float gw = 1.f / (1.f + __expf(-zw));
        int row = so * 32 + bb;
        float4 dv = d4[row * (FF / 4) + c];
        float4 ov;
        ov.x = gx * dv.x;
        ov.y = gy * dv.y;
        ov.z = gz * dv.z;
        ov.w = gw * dv.w;
        o4[row * (FF / 4) + c] = ov;
    }
}

// ---------------------------------------------------------------------------
extern "C" void kernel_launch(void* const* d_in, const int* in_sizes, int n_in,
                              void* d_out, int out_size) {
    const float* data = (const float*)d_in[0];
    const float* attn = (const float*)d_in[1];
    const float* W = (const float*)d_in[2];
    const float* bias = (const float*)d_in[3];
    float* out = (float*)d_out;

    expsum_mma<<<dim3(BB, GT), 256>>>(data, attn);
    final_kernel<<<dim3(BB, 4), 256>>>(data, W, bias, out);
}

// round 7
// speedup vs baseline: 2.0434x; 1.0383x over previous
#include <cuda_runtime.h>
#include <cuda_bf16.h>
#include <cstdint>

#define BB 32
#define SS 16
#define FF 2048
#define GT 16       // g-tiles per batch (128 g each)
#define GTILE 128
#define FTILE 128
#define NFT 16
#define BSTRIDE 18  // words per f-row in B smem (conflict-free for 64b frag loads)

// Scratch (device globals — no allocations allowed)
__device__ float g_Cpart[BB * GT * SS * SS];  // Gram partials per g-tile
__device__ float g_Dpart[BB * GT * SS];       // D partials per g-tile

// pack two fp32 -> bf16x2 {lo=v0, hi=v1}
__device__ __forceinline__ uint32_t pack_bf2(float v0, float v1) {
    uint32_t r;
    asm("cvt.rn.bf16x2.f32 %0, %1, %2;" : "=r"(r) : "f"(v1), "f"(v0));
    return r;
}
__device__ __forceinline__ void mk_pair(float v0, float v1, uint32_t& hi, uint32_t& lo) {
    float h0 = __bfloat162float(__float2bfloat16(v0));
    float h1 = __bfloat162float(__float2bfloat16(v1));
    hi = pack_bf2(v0, v1);
    lo = pack_bf2(v0 - h0, v1 - h1);
}
__device__ __forceinline__ void mma_bf16(float* d, const uint32_t* a, uint32_t b0, uint32_t b1) {
    asm volatile(
        "mma.sync.aligned.m16n8k16.row.col.f32.bf16.bf16.f32 "
        "{%0,%1,%2,%3}, {%4,%5,%6,%7}, {%8,%9}, {%0,%1,%2,%3};"
        : "+f"(d[0]), "+f"(d[1]), "+f"(d[2]), "+f"(d[3])
        : "r"(a[0]), "r"(a[1]), "r"(a[2]), "r"(a[3]), "r"(b0), "r"(b1));
}

// ---------------------------------------------------------------------------
// Kernel 1: tensor-core exp-sum + fused gram + LSE + D-partials.
// Block = (b, gtile of 128 g), 256 threads = 8 warps, warp owns 16 g-rows.
// B word layout per f-row (18 words): hi words at pos(kw)=(kw&3)*2+(kw>>2),
// lo words at 8+pos(kw)  ->  thread frags = 2x LDS.64.
// ---------------------------------------------------------------------------
__global__ void __launch_bounds__(256) expsum_mma(const float* __restrict__ data,
                                                  const float* __restrict__ attn) {
    __shared__ float attnS[SS][129];
    __shared__ __align__(16) uint32_t dataB[2][FTILE * BSTRIDE];
    __shared__ float red[GTILE];

    int tid = threadIdx.x, wid = tid >> 5, lane = tid & 31;
    int b = blockIdx.x, gt = blockIdx.y;
    int gbase = gt * GTILE;

    // attn tile -> smem (fp32, reused for A frags, gram, D-partials)
#pragma unroll
    for (int i = 0; i < 8; i++) {
        int idx = tid + i * 256;
        int s = idx >> 7, gi = idx & 127;
        attnS[s][gi] = attn[(b * SS + s) * FF + gbase + gi];
    }
    __syncthreads();

    // A fragments (fixed per warp). Rows m = lane/4 (+8); cols k = (lane%4)*2 (+1, +8).
    const float LOG2E = 1.442695040888963f;
    int m0 = lane >> 2, k0 = (lane & 3) * 2;
    int gi0 = wid * 16 + m0;
    uint32_t a_hi[4], a_lo[4];
    mk_pair(attnS[k0][gi0] * LOG2E,     attnS[k0 + 1][gi0] * LOG2E,     a_hi[0], a_lo[0]);
    mk_pair(attnS[k0][gi0 + 8] * LOG2E, attnS[k0 + 1][gi0 + 8] * LOG2E, a_hi[1], a_lo[1]);
    mk_pair(attnS[k0 + 8][gi0] * LOG2E, attnS[k0 + 9][gi0] * LOG2E,     a_hi[2], a_lo[2]);
    mk_pair(attnS[k0 + 8][gi0 + 8] * LOG2E, attnS[k0 + 9][gi0 + 8] * LOG2E, a_hi[3], a_lo[3]);

    // Shfl-free converter: thread = (f = tid&127, h = tid>>7), owns kw = h*4+j.
    // Loads s-pairs (2kw, 2kw+1) directly; packs hi and lo words itself.
    int cf = tid & 127, ch = tid >> 7;
    float vp0[4], vp1[4];
    const float* dbase = &data[b * SS * FF];
    auto ldg_tile = [&](int t) {
#pragma unroll
        for (int j = 0; j < 4; j++) {
            int s0 = (ch * 4 + j) * 2;
            vp0[j] = dbase[s0 * FF + t * FTILE + cf];
            vp1[j] = dbase[(s0 + 1) * FF + t * FTILE + cf];
        }
    };
    auto sts_tile = [&](int buf) {
        uint32_t* W = dataB[buf];
#pragma unroll
        for (int j = 0; j < 4; j++) {
            float l0 = vp0[j] - __bfloat162float(__float2bfloat16(vp0[j]));
            float l1 = vp1[j] - __bfloat162float(__float2bfloat16(vp1[j]));
            int pos = j * 2 + ch;  // pos(kw) for kw = h*4+j
            W[cf * BSTRIDE + pos] = pack_bf2(vp0[j], vp1[j]);
            W[cf * BSTRIDE + 8 + pos] = pack_bf2(l0, l1);
        }
    };

    float acc0 = 0.f, acc1 = 0.f;
    int nidx = lane >> 2, kq = lane & 3;

    ldg_tile(0);
    sts_tile(0);
    __syncthreads();
    for (int t = 0; t < NFT; t++) {
        if (t + 1 < NFT) ldg_tile(t + 1);  // LDG latency hidden under MMA loop
        const uint32_t* W = dataB[t & 1];
#pragma unroll 4
        for (int nb = 0; nb < 16; nb++) {
            const uint32_t* wp = &W[(nb * 8 + nidx) * BSTRIDE];
            uint2 bh = *(const uint2*)(wp + kq * 2);      // LDS.64 hi pair
            uint2 bl = *(const uint2*)(wp + 8 + kq * 2);  // LDS.64 lo pair
            float d[4] = {0.f, 0.f, 0.f, 0.f};
            mma_bf16(d, a_lo, bh.x, bh.y);
            mma_bf16(d, a_hi, bl.x, bl.y);
            mma_bf16(d, a_hi, bh.x, bh.y);
            float e0, e1, e2, e3;
            asm("ex2.approx.f32 %0, %1;" : "=f"(e0) : "f"(d[0]));
            asm("ex2.approx.f32 %0, %1;" : "=f"(e1) : "f"(d[1]));
            asm("ex2.approx.f32 %0, %1;" : "=f"(e2) : "f"(d[2]));
            asm("ex2.approx.f32 %0, %1;" : "=f"(e3) : "f"(d[3]));
            acc0 += e0 + e1;
            acc1 += e2 + e3;
        }
        if (t + 1 < NFT) sts_tile((t + 1) & 1);
        __syncthreads();
    }

    // quad-reduce (lanes sharing a D row) -> row exp-sums -> lse
    acc0 += __shfl_xor_sync(0xffffffffu, acc0, 1);
    acc0 += __shfl_xor_sync(0xffffffffu, acc0, 2);
    acc1 += __shfl_xor_sync(0xffffffffu, acc1, 1);
    acc1 += __shfl_xor_sync(0xffffffffu, acc1, 2);
    if (kq == 0) {
        red[gi0] = acc0;
        red[gi0 + 8] = acc1;
    }
    __syncthreads();
    if (tid < 128) red[tid] = logf(red[tid]);
    __syncthreads();

    // D partials: warp w handles s = 2w, 2w+1 over this g-tile
#pragma unroll
    for (int h = 0; h < 2; h++) {
        int s2 = wid * 2 + h;
        float p = 0.f;
#pragma unroll
        for (int k = 0; k < 4; k++) p = fmaf(red[lane + 32 * k], attnS[s2][lane + 32 * k], p);
#pragma unroll
        for (int o = 16; o; o >>= 1) p += __shfl_xor_sync(0xffffffffu, p, o);
        if (lane == 0) g_Dpart[(b * GT + gt) * SS + s2] = p;
    }

    // Gram partial for this g-tile: thread = (s1,s2)
    {
        int s1 = tid >> 4, s2 = tid & 15;
        float acc = 0.f;
#pragma unroll 4
        for (int g = 0; g < GTILE; g++) acc = fmaf(attnS[s1][g], attnS[s2][g], acc);
        g_Cpart[(b * GT + gt) * 256 + tid] = acc;
    }
}

// ---------------------------------------------------------------------------
// Kernel 2: fused combine + final output (float4), grid (32,16) for occupancy.
// ---------------------------------------------------------------------------
__global__ void __launch_bounds__(256) final_kernel(const float* __restrict__ data,
                                                    const float* __restrict__ Wm,
                                                    const float* __restrict__ bias,
                                                    float* __restrict__ out) {
    int bb = blockIdx.x, q = blockIdx.y;
    int tid = threadIdx.x;
    __shared__ float Csm[256], Esm[256], Km[16], Dsm[16];

    {
        float cs = 0.f;
#pragma unroll
        for (int c = 0; c < GT; c++) cs += g_Cpart[(bb * GT + c) * 256 + tid];
        Csm[tid] = cs;
    }
    if (tid < 16) {
        float d = 0.f;
#pragma unroll
        for (int gt = 0; gt < GT; gt++) d += g_Dpart[(bb * GT + gt) * SS + tid];
        Dsm[tid] = d;
    }
    __syncthreads();
    {
        int s = tid >> 4, so = tid & 15;
        float e = Wm[so * 32 + 16 + s];
#pragma unroll
        for (int k = 0; k < SS; k++) e = fmaf(Csm[s * SS + k], Wm[so * 32 + k], e);
        Esm[s * 16 + so] = e;
    }
    if (tid < 16) {
        float c = bias[tid];
#pragma unroll
        for (int k = 0; k < SS; k++) c = fmaf(-Dsm[k], Wm[tid * 32 + k], c);
        Km[tid] = c;
    }
    __syncthreads();

    int c = q * 32 + (tid & 31);  // float4 column 0..511
    int oct = tid >> 5;           // so range [oct*2, oct*2+2)
    const float4* d4 = (const float4*)data;
    float4* o4 = (float4*)out;
    float4 din[SS];
#pragma unroll
    for (int s = 0; s < SS; s++) din[s] = d4[(bb * SS + s) * (FF / 4) + c];
#pragma unroll
    for (int i = 0; i < 2; i++) {
        int so = oct * 2 + i;
        float k0 = Km[so];
        float zx = k0, zy = k0, zz = k0, zw = k0;
#pragma unroll
        for (int s = 0; s < SS; s++) {
            float e = Esm[s * 16 + so];
            zx = fmaf(din[s].x, e, zx);
            zy = fmaf(din[s].y, e, zy);
            zz = fmaf(din[s].z, e, zz);
            zw = fmaf(din[s].w, e, zw);
        }
        float gx = 1.f / (1.f + __expf(-zx));
        float gy = 1.f / (1.f + __expf(-zy));
        float gz = 1.f / (1.f + __expf(-zz));
        float gw = 1.f / (1.f + __expf(-zw));
        int row = so * 32 + bb;
        float4 dv = d4[row * (FF / 4) + c];
        float4 ov;
        ov.x = gx * dv.x;
        ov.y = gy * dv.y;
        ov.z = gz * dv.z;
        ov.w = gw * dv.w;
        o4[row * (FF / 4) + c] = ov;
    }
}

// ---------------------------------------------------------------------------
extern "C" void kernel_launch(void* const* d_in, const int* in_sizes, int n_in,
                              void* d_out, int out_size) {
    const float* data = (const float*)d_in[0];
    const float* attn = (const float*)d_in[1];
    const float* W = (const float*)d_in[2];
    const float* bias = (const float*)d_in[3];
    float* out = (float*)d_out;

    expsum_mma<<<dim3(BB, GT), 256>>>(data, attn);
    final_kernel<<<dim3(BB, GT), 256>>>(data, W, bias, out);
}

// round 8
// speedup vs baseline: 2.1237x; 1.0393x over previous
#include <cuda_runtime.h>
#include <cuda_bf16.h>
#include <cstdint>

#define BB 32
#define SS 16
#define FF 2048
#define GT 16       // g-tiles per batch (128 g each)
#define GTILE 128
#define FTILE 128
#define NFT 16
#define BSTRIDE 18  // words per f-row in B smem (conflict-free for 64b frag loads)

// Scratch (device globals — no allocations allowed)
__device__ float g_Cpart[BB * GT * SS * SS];  // Gram partials per g-tile
__device__ float g_Dpart[BB * GT * SS];       // D partials per g-tile
__device__ float g_E[BB * SS * SS];           // folded gate weights  [b][s*16+so]
__device__ float g_const[BB * SS];            // folded gate constants [b][so]

// pack two fp32 -> bf16x2 {lo=v0, hi=v1}
__device__ __forceinline__ uint32_t pack_bf2(float v0, float v1) {
    uint32_t r;
    asm("cvt.rn.bf16x2.f32 %0, %1, %2;" : "=r"(r) : "f"(v1), "f"(v0));
    return r;
}
__device__ __forceinline__ void mk_pair(float v0, float v1, uint32_t& hi, uint32_t& lo) {
    float h0 = __bfloat162float(__float2bfloat16(v0));
    float h1 = __bfloat162float(__float2bfloat16(v1));
    hi = pack_bf2(v0, v1);
    lo = pack_bf2(v0 - h0, v1 - h1);
}
__device__ __forceinline__ void mma_bf16(float* d, const uint32_t* a, uint32_t b0, uint32_t b1) {
    asm volatile(
        "mma.sync.aligned.m16n8k16.row.col.f32.bf16.bf16.f32 "
        "{%0,%1,%2,%3}, {%4,%5,%6,%7}, {%8,%9}, {%0,%1,%2,%3};"
        : "+f"(d[0]), "+f"(d[1]), "+f"(d[2]), "+f"(d[3])
        : "r"(a[0]), "r"(a[1]), "r"(a[2]), "r"(a[3]), "r"(b0), "r"(b1));
}

// ---------------------------------------------------------------------------
// Kernel 1: tensor-core exp-sum + fused gram + LSE + D-partials.
// ---------------------------------------------------------------------------
__global__ void __launch_bounds__(256, 4) expsum_mma(const float* __restrict__ data,
                                                     const float* __restrict__ attn) {
    __shared__ float attnS[SS][129];
    __shared__ __align__(16) uint32_t dataB[2][FTILE * BSTRIDE];
    __shared__ float red[GTILE];

    int tid = threadIdx.x, wid = tid >> 5, lane = tid & 31;
    int b = blockIdx.x, gt = blockIdx.y;
    int gbase = gt * GTILE;

    // attn tile -> smem (fp32, reused for A frags, gram, D-partials)
#pragma unroll
    for (int i = 0; i < 8; i++) {
        int idx = tid + i * 256;
        int s = idx >> 7, gi = idx & 127;
        attnS[s][gi] = attn[(b * SS + s) * FF + gbase + gi];
    }
    __syncthreads();

    // A fragments (fixed per warp). Rows m = lane/4 (+8); cols k = (lane%4)*2 (+1, +8).
    const float LOG2E = 1.442695040888963f;
    int m0 = lane >> 2, k0 = (lane & 3) * 2;
    int gi0 = wid * 16 + m0;
    uint32_t a_hi[4], a_lo[4];
    mk_pair(attnS[k0][gi0] * LOG2E,     attnS[k0 + 1][gi0] * LOG2E,     a_hi[0], a_lo[0]);
    mk_pair(attnS[k0][gi0 + 8] * LOG2E, attnS[k0 + 1][gi0 + 8] * LOG2E, a_hi[1], a_lo[1]);
    mk_pair(attnS[k0 + 8][gi0] * LOG2E, attnS[k0 + 9][gi0] * LOG2E,     a_hi[2], a_lo[2]);
    mk_pair(attnS[k0 + 8][gi0 + 8] * LOG2E, attnS[k0 + 9][gi0 + 8] * LOG2E, a_hi[3], a_lo[3]);

    // Shfl-free converter: thread = (f = tid&127, h = tid>>7), owns kw = h*4+j.
    int cf = tid & 127, ch = tid >> 7;
    float vp0[4], vp1[4];
    const float* dbase = &data[b * SS * FF];
    auto ldg_tile = [&](int t) {
#pragma unroll
        for (int j = 0; j < 4; j++) {
            int s0 = (ch * 4 + j) * 2;
            vp0[j] = dbase[s0 * FF + t * FTILE + cf];
            vp1[j] = dbase[(s0 + 1) * FF + t * FTILE + cf];
        }
    };
    auto sts_tile = [&](int buf) {
        uint32_t* W = dataB[buf];
#pragma unroll
        for (int j = 0; j < 4; j++) {
            float l0 = vp0[j] - __bfloat162float(__float2bfloat16(vp0[j]));
            float l1 = vp1[j] - __bfloat162float(__float2bfloat16(vp1[j]));
            int pos = j * 2 + ch;  // pos(kw) for kw = h*4+j
            W[cf * BSTRIDE + pos] = pack_bf2(vp0[j], vp1[j]);
            W[cf * BSTRIDE + 8 + pos] = pack_bf2(l0, l1);
        }
    };

    float acc0 = 0.f, acc1 = 0.f;
    int nidx = lane >> 2, kq = lane & 3;

    ldg_tile(0);
    sts_tile(0);
    __syncthreads();
    for (int t = 0; t < NFT; t++) {
        if (t + 1 < NFT) ldg_tile(t + 1);  // LDG latency hidden under MMA loop
        const uint32_t* W = dataB[t & 1];
#pragma unroll 8
        for (int nb = 0; nb < 16; nb++) {
            const uint32_t* wp = &W[(nb * 8 + nidx) * BSTRIDE];
            uint2 bh = *(const uint2*)(wp + kq * 2);      // LDS.64 hi pair
            uint2 bl = *(const uint2*)(wp + 8 + kq * 2);  // LDS.64 lo pair
            float d[4] = {0.f, 0.f, 0.f, 0.f};
            mma_bf16(d, a_lo, bh.x, bh.y);
            mma_bf16(d, a_hi, bl.x, bl.y);
            mma_bf16(d, a_hi, bh.x, bh.y);
            float e0, e1, e2, e3;
            asm("ex2.approx.f32 %0, %1;" : "=f"(e0) : "f"(d[0]));
            asm("ex2.approx.f32 %0, %1;" : "=f"(e1) : "f"(d[1]));
            asm("ex2.approx.f32 %0, %1;" : "=f"(e2) : "f"(d[2]));
            asm("ex2.approx.f32 %0, %1;" : "=f"(e3) : "f"(d[3]));
            acc0 += e0 + e1;
            acc1 += e2 + e3;
        }
        if (t + 1 < NFT) sts_tile((t + 1) & 1);
        __syncthreads();
    }

    // quad-reduce (lanes sharing a D row) -> row exp-sums -> lse
    acc0 += __shfl_xor_sync(0xffffffffu, acc0, 1);
    acc0 += __shfl_xor_sync(0xffffffffu, acc0, 2);
    acc1 += __shfl_xor_sync(0xffffffffu, acc1, 1);
    acc1 += __shfl_xor_sync(0xffffffffu, acc1, 2);
    if (kq == 0) {
        red[gi0] = acc0;
        red[gi0 + 8] = acc1;
    }
    __syncthreads();
    if (tid < 128) red[tid] = logf(red[tid]);
    __syncthreads();

    // D partials: warp w handles s = 2w, 2w+1 over this g-tile
#pragma unroll
    for (int h = 0; h < 2; h++) {
        int s2 = wid * 2 + h;
        float p = 0.f;
#pragma unroll
        for (int k = 0; k < 4; k++) p = fmaf(red[lane + 32 * k], attnS[s2][lane + 32 * k], p);
#pragma unroll
        for (int o = 16; o; o >>= 1) p += __shfl_xor_sync(0xffffffffu, p, o);
        if (lane == 0) g_Dpart[(b * GT + gt) * SS + s2] = p;
    }

    // Gram partial for this g-tile: thread = (s1,s2)
    {
        int s1 = tid >> 4, s2 = tid & 15;
        float acc = 0.f;
#pragma unroll 4
        for (int g = 0; g < GTILE; g++) acc = fmaf(attnS[s1][g], attnS[s2][g], acc);
        g_Cpart[(b * GT + gt) * 256 + tid] = acc;
    }
}

// ---------------------------------------------------------------------------
// Kernel 2: combine (once per batch) -> g_E, g_const.
// ---------------------------------------------------------------------------
__global__ void __launch_bounds__(256) combine_kernel(const float* __restrict__ Wm,
                                                      const float* __restrict__ bias) {
    int bb = blockIdx.x;
    int tid = threadIdx.x;
    __shared__ float Csm[256], Dsm[16];
    {
        float cs = 0.f;
#pragma unroll
        for (int c = 0; c < GT; c++) cs += g_Cpart[(bb * GT + c) * 256 + tid];
        Csm[tid] = cs;
    }
    if (tid < 16) {
        float d = 0.f;
#pragma unroll
        for (int gt = 0; gt < GT; gt++) d += g_Dpart[(bb * GT + gt) * SS + tid];
        Dsm[tid] = d;
    }
    __syncthreads();
    {
        int s = tid >> 4, so = tid & 15;
        float e = Wm[so * 32 + 16 + s];
#pragma unroll
        for (int k = 0; k < SS; k++) e = fmaf(Csm[s * SS + k], Wm[so * 32 + k], e);
        g_E[bb * 256 + s * 16 + so] = e;
    }
    if (tid < 16) {
        float c = bias[tid];
#pragma unroll
        for (int k = 0; k < SS; k++) c = fmaf(-Dsm[k], Wm[tid * 32 + k], c);
        g_const[bb * SS + tid] = c;
    }
}

// ---------------------------------------------------------------------------
// Kernel 3: final output stream (float4), grid (32,16), no combine work.
// ---------------------------------------------------------------------------
__global__ void __launch_bounds__(256) final_kernel(const float* __restrict__ data,
                                                    float* __restrict__ out) {
    int bb = blockIdx.x, q = blockIdx.y;
    int tid = threadIdx.x;
    __shared__ float Esm[256], Km[16];
    Esm[tid] = g_E[bb * 256 + tid];
    if (tid < 16) Km[tid] = g_const[bb * SS + tid];
    __syncthreads();

    int c = q * 32 + (tid & 31);  // float4 column 0..511
    int oct = tid >> 5;           // so range [oct*2, oct*2+2)
    const float4* d4 = (const float4*)data;
    float4* o4 = (float4*)out;
    float4 din[SS];
#pragma unroll
    for (int s = 0; s < SS; s++) din[s] = d4[(bb * SS + s) * (FF / 4) + c];
#pragma unroll
    for (int i = 0; i < 2; i++) {
        int so = oct * 2 + i;
        float k0 = Km[so];
        float zx = k0, zy = k0, zz = k0, zw = k0;
#pragma unroll
        for (int s = 0; s < SS; s++) {
            float e = Esm[s * 16 + so];
            zx = fmaf(din[s].x, e, zx);
            zy = fmaf(din[s].y, e, zy);
            zz = fmaf(din[s].z, e, zz);
            zw = fmaf(din[s].w, e, zw);
        }
        float gx = 1.f / (1.f + __expf(-zx));
        float gy = 1.f / (1.f + __expf(-zy));
        float gz = 1.f / (1.f + __expf(-zz));
        float gw = 1.f / (1.f + __expf(-zw));
        int row = so * 32 + bb;
        float4 dv = d4[row * (FF / 4) + c];
        float4 ov;
        ov.x = gx * dv.x;
        ov.y = gy * dv.y;
        ov.z = gz * dv.z;
        ov.w = gw * dv.w;
        o4[row * (FF / 4) + c] = ov;
    }
}

// ---------------------------------------------------------------------------
extern "C" void kernel_launch(void* const* d_in, const int* in_sizes, int n_in,
                              void* d_out, int out_size) {
    const float* data = (const float*)d_in[0];
    const float* attn = (const float*)d_in[1];
    const float* W = (const float*)d_in[2];
    const float* bias = (const float*)d_in[3];
    float* out = (float*)d_out;

    expsum_mma<<<dim3(BB, GT), 256>>>(data, attn);
    combine_kernel<<<BB, 256>>>(W, bias);
    final_kernel<<<dim3(BB, GT), 256>>>(data, out);
}